// round 1
// baseline (speedup 1.0000x reference)
#include <cuda_runtime.h>
#include <cstdint>

#define D 96
#define MAX_N 50000

// Scratch accumulator: initialized to x each launch, scatter-added, then GEMM'd.
__device__ float g_aggr[MAX_N * D];

// ---------------------------------------------------------------------------
// Kernel 1: g_aggr = x   (folds the +x residual into the aggregate)
// ---------------------------------------------------------------------------
__global__ void init_kernel(const float* __restrict__ x, int n4) {
    int i = blockIdx.x * blockDim.x + threadIdx.x;
    if (i < n4) {
        reinterpret_cast<float4*>(g_aggr)[i] =
            reinterpret_cast<const float4*>(x)[i];
    }
}

// ---------------------------------------------------------------------------
// Kernel 2: per-edge gather-scale + scatter-add.
// Thread layout: threadIdx.x = float4 chunk (0..23), threadIdx.y = edge slot.
// Uses red.global.add.v4.f32 (sm_90+) -> 1 vector REDG per 16B instead of 4
// scalar atomics. x and g_aggr both fit in L2, so gathers/atomics are L2-hit.
// ---------------------------------------------------------------------------
__global__ void scatter_kernel(const float* __restrict__ x,
                               const int*   __restrict__ ei,
                               const float* __restrict__ ew,
                               const float* __restrict__ pr,
                               int E) {
    int eid = blockIdx.x * blockDim.y + threadIdx.y;
    if (eid >= E) return;
    int c = threadIdx.x;                       // 0..23 (float4 chunks of 96)

    int   src = __ldg(ei + eid);
    int   dst = __ldg(ei + E + eid);
    float w   = __ldg(ew + eid) * __ldg(pr + src);

    float4 v = __ldg(reinterpret_cast<const float4*>(x + (size_t)src * D) + c);

    float* o = g_aggr + (size_t)dst * D + c * 4;
    asm volatile("red.global.add.v4.f32 [%0], {%1, %2, %3, %4};"
                 :: "l"(o), "f"(v.x * w), "f"(v.y * w),
                    "f"(v.z * w), "f"(v.w * w)
                 : "memory");
}

// ---------------------------------------------------------------------------
// Kernel 3: out = g_aggr @ W^T + b
// Block = 384 threads (96 cols x 4 row-groups), 32 rows per block.
// Per-thread rotated d-iteration (d = (k+col) % 96) makes both sW and sA
// shared reads bank-conflict-free without padding (96 % 32 == 0 trick).
// Static smem: 96*96*4 + 32*96*4 = 49152 B (exactly the 48KB static limit).
// ---------------------------------------------------------------------------
__global__ void gemm_kernel(const float* __restrict__ Wm,
                            const float* __restrict__ b,
                            float* __restrict__ out,
                            int N) {
    __shared__ float sW[D * D];
    __shared__ float sA[32 * D];

    int t   = threadIdx.x;          // 0..383
    int col = t % D;                // output column
    int rg  = t / D;                // row group 0..3 (8 rows each)

    for (int i = t; i < D * D; i += 384)
        sW[i] = Wm[i];

    int row0 = blockIdx.x * 32;
    for (int i = t; i < 32 * D; i += 384) {
        int gr = row0 + i / D;
        sA[i] = (gr < N) ? g_aggr[(size_t)gr * D + (i % D)] : 0.0f;
    }
    __syncthreads();

    float acc[8] = {0.f, 0.f, 0.f, 0.f, 0.f, 0.f, 0.f, 0.f};

#pragma unroll 4
    for (int k = 0; k < D; k++) {
        int d = k + col;
        if (d >= D) d -= D;
        float w = sW[col * D + d];          // bank = (k+col)%32 -> conflict-free
#pragma unroll
        for (int r = 0; r < 8; r++)
            acc[r] += sA[(rg * 8 + r) * D + d] * w;  // bank = (k+col)%32 -> conflict-free
    }

    float bb = __ldg(b + col);
#pragma unroll
    for (int r = 0; r < 8; r++) {
        int gr = row0 + rg * 8 + r;
        if (gr < N)
            out[(size_t)gr * D + col] = acc[r] + bb;
    }
}

// ---------------------------------------------------------------------------
// Launch
// Inputs (metadata order): x[N*D] f32, edge_index[2*E] i32, edge_weight[E] f32,
//                          pagerank[N] f32, W[D*D] f32, b[D] f32. Output f32 [N,D].
// ---------------------------------------------------------------------------
extern "C" void kernel_launch(void* const* d_in, const int* in_sizes, int n_in,
                              void* d_out, int out_size) {
    const float* x  = (const float*)d_in[0];
    const int*   ei = (const int*)  d_in[1];
    const float* ew = (const float*)d_in[2];
    const float* pr = (const float*)d_in[3];
    const float* Wm = (const float*)d_in[4];
    const float* b  = (const float*)d_in[5];
    float* out = (float*)d_out;

    int N = in_sizes[0] / D;
    int E = in_sizes[1] / 2;

    int n4 = N * D / 4;
    init_kernel<<<(n4 + 255) / 256, 256>>>(x, n4);

    dim3 bdim(24, 8);                       // 24 chunks x 8 edges = 192 threads
    scatter_kernel<<<(E + 7) / 8, bdim>>>(x, ei, ew, pr, E);

    gemm_kernel<<<(N + 31) / 32, 384>>>(Wm, b, out, N);
}